// round 2
// baseline (speedup 1.0000x reference)
#include <cuda_runtime.h>
#include <math.h>

#define BB  2
#define SS  2048
#define HH  4096
#define NH  32
#define NKV 8
#define HD  128
#define MR  (BB * SS)      // 4096 rows
#define QD  (NH * HD)      // 4096
#define KVD (NKV * HD)     // 1024

// Scratch (device globals; no runtime allocation allowed)
__device__ float g_q[MR * QD];     // 64 MB
__device__ float g_k[MR * KVD];    // 16 MB
__device__ float g_v[MR * KVD];    // 16 MB
__device__ float g_att[MR * QD];   // 64 MB

// ---------------------------------------------------------------------------
// Tiled fp32 GEMM: C[M,N] = A[M,K] @ B[K,N], all dims multiples of 128/16.
// 128x128 block tile, K-tile 16, 256 threads, 8x8 per-thread microtile.
// ---------------------------------------------------------------------------
__global__ __launch_bounds__(256) void gemm128(const float* __restrict__ A,
                                               const float* __restrict__ Bm,
                                               float* __restrict__ C,
                                               int Mdim, int Ndim, int Kdim) {
    __shared__ float As[16][128];  // transposed A tile: As[k][row]
    __shared__ float Bs[16][128];  // Bs[k][col]

    const int tid = threadIdx.x;
    const int tx  = tid & 15;
    const int ty  = tid >> 4;
    const int bn  = blockIdx.x * 128;
    const int bm  = blockIdx.y * 128;

    float acc[8][8];
#pragma unroll
    for (int i = 0; i < 8; i++)
#pragma unroll
        for (int j = 0; j < 8; j++) acc[i][j] = 0.f;

    for (int k0 = 0; k0 < Kdim; k0 += 16) {
#pragma unroll
        for (int i = 0; i < 2; i++) {
            int idx = i * 256 + tid;            // 0..511
            int row = idx >> 2;                 // 0..127
            int kq  = (idx & 3) << 2;           // 0,4,8,12
            float4 a = *(const float4*)&A[(size_t)(bm + row) * Kdim + k0 + kq];
            As[kq + 0][row] = a.x;
            As[kq + 1][row] = a.y;
            As[kq + 2][row] = a.z;
            As[kq + 3][row] = a.w;
            int kk = idx >> 5;                  // 0..15
            int n4 = (idx & 31) << 2;           // 0..124
            *(float4*)&Bs[kk][n4] =
                *(const float4*)&Bm[(size_t)(k0 + kk) * Ndim + bn + n4];
        }
        __syncthreads();
#pragma unroll
        for (int kk = 0; kk < 16; kk++) {
            float a[8], b[8];
            *(float4*)&a[0] = *(float4*)&As[kk][ty * 4];
            *(float4*)&a[4] = *(float4*)&As[kk][64 + ty * 4];
            *(float4*)&b[0] = *(float4*)&Bs[kk][tx * 4];
            *(float4*)&b[4] = *(float4*)&Bs[kk][64 + tx * 4];
#pragma unroll
            for (int i = 0; i < 8; i++)
#pragma unroll
                for (int j = 0; j < 8; j++) acc[i][j] = fmaf(a[i], b[j], acc[i][j]);
        }
        __syncthreads();
    }

#pragma unroll
    for (int i = 0; i < 8; i++) {
        int row = bm + ((i < 4) ? (ty * 4 + i) : (60 + ty * 4 + i));
        float4 c0 = make_float4(acc[i][0], acc[i][1], acc[i][2], acc[i][3]);
        float4 c1 = make_float4(acc[i][4], acc[i][5], acc[i][6], acc[i][7]);
        *(float4*)&C[(size_t)row * Ndim + bn + tx * 4] = c0;
        *(float4*)&C[(size_t)row * Ndim + bn + 64 + tx * 4] = c1;
    }
}

// ---------------------------------------------------------------------------
// RoPE (in place): buf is [MR][nheads*128]; pairs (i, i+64) rotated by
// angle = pos * theta^(-i/64).  Position = row % SS (position_ids is
// tile(arange(S)) by construction — avoids int32/int64 dtype ambiguity).
// ---------------------------------------------------------------------------
__global__ void rope_kernel(float* __restrict__ buf, int nheads) {
    int idx = blockIdx.x * blockDim.x + threadIdx.x;
    int total = MR * nheads * 64;
    if (idx >= total) return;
    int i    = idx & 63;
    int head = (idx >> 6) % nheads;
    int row  = idx / (nheads << 6);

    float p    = (float)(row % SS);
    // inv_freq = 10000^(-i/64) = exp(-i * ln(10000)/64)
    float invf = expf(-(float)i * 0.14391156831212787f);
    float ang  = p * invf;
    float c, s;
    sincosf(ang, &s, &c);

    size_t base = (size_t)row * (nheads * HD) + head * HD + i;
    float x0 = buf[base];
    float x1 = buf[base + 64];
    buf[base]      = x0 * c - x1 * s;
    buf[base + 64] = x1 * c + x0 * s;
}

// ---------------------------------------------------------------------------
// Causal flash attention with GQA (4 query heads per kv head).
// Block: (q-tile of 64, head, batch). 256 threads: 16x16 grid; each thread
// owns 4 score rows x 4 strided cols and an O slice of 4 rows x 8 dims.
// ---------------------------------------------------------------------------
#define BQ 64
#define BK 64
#define KP 132   // pitch for Qs/Ks rows (128 + 4; keeps 16B alignment, 2-way max conflicts)
#define PP 68    // pitch for P tile
#define ATTN_SMEM ((BQ * KP + BK * KP + BK * HD + BQ * PP) * 4)

__global__ __launch_bounds__(256) void attn_kernel(const float* __restrict__ Q,
                                                   const float* __restrict__ Kg,
                                                   const float* __restrict__ Vg,
                                                   float* __restrict__ O) {
    extern __shared__ float sm[];
    float* Qs = sm;                 // [BQ][KP]
    float* Ks = Qs + BQ * KP;       // [BK][KP]
    float* Vs = Ks + BK * KP;       // [BK][HD]
    float* Ps = Vs + BK * HD;       // [BQ][PP]

    const int tid = threadIdx.x;
    const int tx  = tid & 15;
    const int ty  = tid >> 4;
    const int qb  = blockIdx.x;
    const int h   = blockIdx.y;
    const int b   = blockIdx.z;
    const int kvh = h >> 2;         // NH/NKV = 4
    const int q0  = qb * BQ;

    // Load Q tile (64 rows x 128 dims)
#pragma unroll
    for (int i = 0; i < 8; i++) {
        int idx = i * 256 + tid;
        int r   = idx >> 5;
        int d4  = (idx & 31) << 2;
        *(float4*)&Qs[r * KP + d4] =
            *(const float4*)&Q[(size_t)(b * SS + q0 + r) * QD + h * HD + d4];
    }

    float m_i[4], l_i[4], acc[4][8];
#pragma unroll
    for (int i = 0; i < 4; i++) {
        m_i[i] = -1e30f;
        l_i[i] = 0.f;
#pragma unroll
        for (int d = 0; d < 8; d++) acc[i][d] = 0.f;
    }
    const float scale = 0.08838834764831845f;  // 1/sqrt(128)

    for (int kb = 0; kb <= qb; kb++) {
        const int k0 = kb * BK;
        __syncthreads();  // previous iteration's reads of Ks/Vs complete
#pragma unroll
        for (int i = 0; i < 8; i++) {
            int idx = i * 256 + tid;
            int r   = idx >> 5;
            int d4  = (idx & 31) << 2;
            size_t g = (size_t)(b * SS + k0 + r) * KVD + kvh * HD + d4;
            *(float4*)&Ks[r * KP + d4] = *(const float4*)&Kg[g];
            *(float4*)&Vs[r * HD + d4] = *(const float4*)&Vg[g];
        }
        __syncthreads();

        // S = Q K^T for this tile: rows ty*4+i, cols tx + 16*j
        float sc[4][4];
#pragma unroll
        for (int i = 0; i < 4; i++)
#pragma unroll
            for (int j = 0; j < 4; j++) sc[i][j] = 0.f;

#pragma unroll 8
        for (int d4 = 0; d4 < HD; d4 += 4) {
            float4 qv[4], kv[4];
#pragma unroll
            for (int i = 0; i < 4; i++)
                qv[i] = *(float4*)&Qs[(ty * 4 + i) * KP + d4];
#pragma unroll
            for (int j = 0; j < 4; j++)
                kv[j] = *(float4*)&Ks[(tx + 16 * j) * KP + d4];
#pragma unroll
            for (int i = 0; i < 4; i++)
#pragma unroll
                for (int j = 0; j < 4; j++) {
                    sc[i][j] = fmaf(qv[i].x, kv[j].x, sc[i][j]);
                    sc[i][j] = fmaf(qv[i].y, kv[j].y, sc[i][j]);
                    sc[i][j] = fmaf(qv[i].z, kv[j].z, sc[i][j]);
                    sc[i][j] = fmaf(qv[i].w, kv[j].w, sc[i][j]);
                }
        }

        // scale + causal mask
#pragma unroll
        for (int i = 0; i < 4; i++) {
            int gr = q0 + ty * 4 + i;
#pragma unroll
            for (int j = 0; j < 4; j++) {
                int gc = k0 + tx + 16 * j;
                float v = sc[i][j] * scale;
                sc[i][j] = (gc > gr) ? -1e30f : v;
            }
        }

        // online softmax (row reductions across the 16 tx lanes of this ty group)
#pragma unroll
        for (int i = 0; i < 4; i++) {
            float mx = fmaxf(fmaxf(sc[i][0], sc[i][1]), fmaxf(sc[i][2], sc[i][3]));
#pragma unroll
            for (int off = 1; off < 16; off <<= 1)
                mx = fmaxf(mx, __shfl_xor_sync(0xffffffffu, mx, off));
            float m_new = fmaxf(m_i[i], mx);
            float corr  = __expf(m_i[i] - m_new);
            float rs = 0.f;
#pragma unroll
            for (int j = 0; j < 4; j++) {
                float p = __expf(sc[i][j] - m_new);
                sc[i][j] = p;
                rs += p;
            }
#pragma unroll
            for (int off = 1; off < 16; off <<= 1)
                rs += __shfl_xor_sync(0xffffffffu, rs, off);
            l_i[i] = l_i[i] * corr + rs;
            m_i[i] = m_new;
#pragma unroll
            for (int d = 0; d < 8; d++) acc[i][d] *= corr;
#pragma unroll
            for (int j = 0; j < 4; j++)
                Ps[(ty * 4 + i) * PP + tx + 16 * j] = sc[i][j];
        }
        __syncwarp();  // Ps rows for this ty group written by this warp only

        // O += P @ V : thread handles its 4 rows x 8 dims (d = tx*8 .. +8)
#pragma unroll 4
        for (int c = 0; c < BK; c++) {
            float4 v0 = *(float4*)&Vs[c * HD + tx * 8];
            float4 v1 = *(float4*)&Vs[c * HD + tx * 8 + 4];
            float pr[4];
#pragma unroll
            for (int i = 0; i < 4; i++) pr[i] = Ps[(ty * 4 + i) * PP + c];
#pragma unroll
            for (int i = 0; i < 4; i++) {
                acc[i][0] = fmaf(pr[i], v0.x, acc[i][0]);
                acc[i][1] = fmaf(pr[i], v0.y, acc[i][1]);
                acc[i][2] = fmaf(pr[i], v0.z, acc[i][2]);
                acc[i][3] = fmaf(pr[i], v0.w, acc[i][3]);
                acc[i][4] = fmaf(pr[i], v1.x, acc[i][4]);
                acc[i][5] = fmaf(pr[i], v1.y, acc[i][5]);
                acc[i][6] = fmaf(pr[i], v1.z, acc[i][6]);
                acc[i][7] = fmaf(pr[i], v1.w, acc[i][7]);
            }
        }
    }

    // finalize: O / l, write [row][h*128 + d] layout for the output GEMM
#pragma unroll
    for (int i = 0; i < 4; i++) {
        float il = 1.f / l_i[i];
        float4 o0 = make_float4(acc[i][0] * il, acc[i][1] * il,
                                acc[i][2] * il, acc[i][3] * il);
        float4 o1 = make_float4(acc[i][4] * il, acc[i][5] * il,
                                acc[i][6] * il, acc[i][7] * il);
        size_t g = (size_t)(b * SS + q0 + ty * 4 + i) * QD + h * HD + tx * 8;
        *(float4*)&O[g]     = o0;
        *(float4*)&O[g + 4] = o1;
    }
}

// ---------------------------------------------------------------------------
extern "C" void kernel_launch(void* const* d_in, const int* in_sizes, int n_in,
                              void* d_out, int out_size) {
    const float* hs  = (const float*)d_in[0];
    const float* Wq  = (const float*)d_in[2];
    const float* Wk  = (const float*)d_in[3];
    const float* Wv  = (const float*)d_in[4];
    const float* Wo  = (const float*)d_in[5];
    float*       out = (float*)d_out;

    float *qb, *kb, *vb, *ab;
    cudaGetSymbolAddress((void**)&qb, g_q);
    cudaGetSymbolAddress((void**)&kb, g_k);
    cudaGetSymbolAddress((void**)&vb, g_v);
    cudaGetSymbolAddress((void**)&ab, g_att);

    // QKV projections
    gemm128<<<dim3(QD / 128, MR / 128), 256>>>(hs, Wq, qb, MR, QD, HH);
    gemm128<<<dim3(KVD / 128, MR / 128), 256>>>(hs, Wk, kb, MR, KVD, HH);
    gemm128<<<dim3(KVD / 128, MR / 128), 256>>>(hs, Wv, vb, MR, KVD, HH);

    // RoPE on q and k
    rope_kernel<<<(MR * NH * 64 + 255) / 256, 256>>>(qb, NH);
    rope_kernel<<<(MR * NKV * 64 + 255) / 256, 256>>>(kb, NKV);

    // causal GQA attention
    cudaFuncSetAttribute(attn_kernel,
                         cudaFuncAttributeMaxDynamicSharedMemorySize, ATTN_SMEM);
    attn_kernel<<<dim3(SS / BQ, NH, BB), 256, ATTN_SMEM>>>(qb, kb, vb, ab);

    // output projection
    gemm128<<<dim3(QD / 128, MR / 128), 256>>>(ab, Wo, out, MR, QD, QD);
}

// round 4
// speedup vs baseline: 2.7918x; 2.7918x over previous
#include <cuda_runtime.h>
#include <cuda_bf16.h>
#include <math.h>
#include <stdint.h>

#define BB  2
#define SS  2048
#define HH  4096
#define NH  32
#define NKV 8
#define HD  128
#define MR  (BB * SS)      // 4096 rows
#define QD  (NH * HD)      // 4096
#define KVD (NKV * HD)     // 1024

// ---------------- scratch (device globals; no runtime allocation) ----------
__device__ float g_q[MR * QD];
__device__ float g_k[MR * KVD];
__device__ float g_v[MR * KVD];
__device__ float g_att[MR * QD];

__device__ __nv_bfloat16 g_hs_h[MR * HH];
__device__ __nv_bfloat16 g_hs_l[MR * HH];
__device__ __nv_bfloat16 g_wqT_h[QD * HH];
__device__ __nv_bfloat16 g_wqT_l[QD * HH];
__device__ __nv_bfloat16 g_wkT_h[KVD * HH];
__device__ __nv_bfloat16 g_wkT_l[KVD * HH];
__device__ __nv_bfloat16 g_wvT_h[KVD * HH];
__device__ __nv_bfloat16 g_wvT_l[KVD * HH];
__device__ __nv_bfloat16 g_woT_h[HH * QD];
__device__ __nv_bfloat16 g_woT_l[HH * QD];
__device__ __nv_bfloat16 g_att_h[MR * QD];
__device__ __nv_bfloat16 g_att_l[MR * QD];

// ---------------- PTX helpers ----------------------------------------------
__device__ __forceinline__ uint32_t smem_u32(const void* p) {
    uint32_t a;
    asm("{ .reg .u64 t; cvta.to.shared.u64 t, %1; cvt.u32.u64 %0, t; }"
        : "=r"(a) : "l"(p));
    return a;
}
__device__ __forceinline__ void cpasync16(uint32_t dst, const void* src) {
    asm volatile("cp.async.cg.shared.global [%0], [%1], 16;"
                 :: "r"(dst), "l"(src));
}
#define CP_COMMIT() asm volatile("cp.async.commit_group;" ::: "memory")
#define CP_WAIT0()  asm volatile("cp.async.wait_group 0;" ::: "memory")

#define LDSM4(r0, r1, r2, r3, addr) \
    asm volatile("ldmatrix.sync.aligned.m8n8.x4.shared.b16 {%0,%1,%2,%3}, [%4];" \
                 : "=r"(r0), "=r"(r1), "=r"(r2), "=r"(r3) : "r"(addr))

#define MMA_BF16(c, a, b) \
    asm volatile("mma.sync.aligned.m16n8k16.row.col.f32.bf16.bf16.f32 " \
                 "{%0,%1,%2,%3}, {%4,%5,%6,%7}, {%8,%9}, {%0,%1,%2,%3};" \
                 : "+f"((c)[0]), "+f"((c)[1]), "+f"((c)[2]), "+f"((c)[3]) \
                 : "r"((a)[0]), "r"((a)[1]), "r"((a)[2]), "r"((a)[3]), \
                   "r"((b)[0]), "r"((b)[1]))

// ---------------------------------------------------------------------------
// fp32 -> bf16 hi/lo split (elementwise, vectorized by 4)
// ---------------------------------------------------------------------------
__global__ void split_kernel(const float* __restrict__ src,
                             __nv_bfloat16* __restrict__ hi,
                             __nv_bfloat16* __restrict__ lo, int n4) {
    int i = blockIdx.x * blockDim.x + threadIdx.x;
    if (i >= n4) return;
    float4 s = ((const float4*)src)[i];
    __nv_bfloat162 h01 = __floats2bfloat162_rn(s.x, s.y);
    __nv_bfloat162 h23 = __floats2bfloat162_rn(s.z, s.w);
    float2 f01 = __bfloat1622float2(h01);
    float2 f23 = __bfloat1622float2(h23);
    __nv_bfloat162 l01 = __floats2bfloat162_rn(s.x - f01.x, s.y - f01.y);
    __nv_bfloat162 l23 = __floats2bfloat162_rn(s.z - f23.x, s.w - f23.y);
    ((__nv_bfloat162*)hi)[2 * i]     = h01;
    ((__nv_bfloat162*)hi)[2 * i + 1] = h23;
    ((__nv_bfloat162*)lo)[2 * i]     = l01;
    ((__nv_bfloat162*)lo)[2 * i + 1] = l23;
}

// ---------------------------------------------------------------------------
// Weight transpose + split: W[K,N] fp32 -> hiT/loT [N,K] bf16
// ---------------------------------------------------------------------------
__global__ void split_transpose(const float* __restrict__ W,
                                __nv_bfloat16* __restrict__ hiT,
                                __nv_bfloat16* __restrict__ loT, int K, int N) {
    __shared__ float t[32][33];
    int n0 = blockIdx.x * 32, k0 = blockIdx.y * 32;
    int tx = threadIdx.x, ty = threadIdx.y;
#pragma unroll
    for (int i = 0; i < 32; i += 8)
        t[ty + i][tx] = W[(size_t)(k0 + ty + i) * N + n0 + tx];
    __syncthreads();
#pragma unroll
    for (int i = 0; i < 32; i += 8) {
        float v = t[tx][ty + i];
        __nv_bfloat16 h = __float2bfloat16_rn(v);
        __nv_bfloat16 l = __float2bfloat16_rn(v - __bfloat162float(h));
        size_t o = (size_t)(n0 + ty + i) * K + k0 + tx;
        hiT[o] = h;
        loT[o] = l;
    }
}

// ---------------------------------------------------------------------------
// mma.sync bf16x3 GEMM: C[M,N] = A[M,K] @ BT[N,K]^T  (fp32-accurate)
// 128x128 tile, BK=32, 256 threads (8 warps, 2x4), 64x32 warp tile.
// cp.async double-buffered; 80B row pitch => conflict-free ldmatrix.
// ---------------------------------------------------------------------------
#define TILE_B   10240               // one 128x32 bf16 tile w/ pitch 80B
#define STAGE_B  (4 * TILE_B)        // Ah, Al, Bh, Bl
#define GEMM_SMEM (2 * STAGE_B)      // 81920 bytes

__global__ __launch_bounds__(256, 1)
void mma_gemm(const __nv_bfloat16* __restrict__ Ahi,
              const __nv_bfloat16* __restrict__ Alo,
              const __nv_bfloat16* __restrict__ Bhi,
              const __nv_bfloat16* __restrict__ Blo,
              float* __restrict__ C, int Nd, int Kd) {
    extern __shared__ char smem[];
    const uint32_t sb = smem_u32(smem);
    const int tid = threadIdx.x;
    const int wid = tid >> 5, lid = tid & 31;
    const int wm = wid >> 2, wn = wid & 3;
    const int bn = blockIdx.x * 128, bm = blockIdx.y * 128;

    float c[4][4][4];
#pragma unroll
    for (int i = 0; i < 4; i++)
#pragma unroll
        for (int j = 0; j < 4; j++)
#pragma unroll
            for (int q = 0; q < 4; q++) c[i][j][q] = 0.f;

    // ldmatrix per-lane source coords
    const int rowA = lid & 15;
    const int khA  = (lid >> 4) << 3;
    const int nB   = ((lid >> 4) << 3) + (lid & 7);
    const int khB  = ((lid >> 3) & 1) << 3;

#define LOAD_STAGE(s, k0)                                                     \
    do {                                                                      \
        _Pragma("unroll")                                                     \
        for (int li = 0; li < 2; li++) {                                      \
            int id  = li * 256 + tid;                                         \
            int row = id >> 2, seg = id & 3;                                  \
            uint32_t so = sb + (s) * STAGE_B + row * 80 + seg * 16;           \
            size_t ga = (size_t)(bm + row) * Kd + (k0) + seg * 8;             \
            size_t gb = (size_t)(bn + row) * Kd + (k0) + seg * 8;             \
            cpasync16(so,              Ahi + ga);                             \
            cpasync16(so + TILE_B,     Alo + ga);                             \
            cpasync16(so + 2 * TILE_B, Bhi + gb);                             \
            cpasync16(so + 3 * TILE_B, Blo + gb);                             \
        }                                                                     \
        CP_COMMIT();                                                          \
    } while (0)

    const int nk = Kd >> 5;  // K / 32
    LOAD_STAGE(0, 0);

    for (int kt = 0; kt < nk; kt++) {
        CP_WAIT0();
        __syncthreads();
        if (kt + 1 < nk) LOAD_STAGE((kt + 1) & 1, (kt + 1) << 5);

        const uint32_t abase = sb + (kt & 1) * STAGE_B;
        const uint32_t bbase = abase + 2 * TILE_B;
#pragma unroll
        for (int kk = 0; kk < 32; kk += 16) {
            uint32_t bh[4][2], bl[4][2];
#pragma unroll
            for (int j2 = 0; j2 < 2; j2++) {
                uint32_t ba = bbase + (wn * 32 + j2 * 16 + nB) * 80 +
                              (kk + khB) * 2;
                LDSM4(bh[j2 * 2][0], bh[j2 * 2][1],
                      bh[j2 * 2 + 1][0], bh[j2 * 2 + 1][1], ba);
                LDSM4(bl[j2 * 2][0], bl[j2 * 2][1],
                      bl[j2 * 2 + 1][0], bl[j2 * 2 + 1][1], ba + TILE_B);
            }
#pragma unroll
            for (int i = 0; i < 4; i++) {
                uint32_t aa = abase + (wm * 64 + i * 16 + rowA) * 80 +
                              (kk + khA) * 2;
                uint32_t ah[4], al[4];
                LDSM4(ah[0], ah[1], ah[2], ah[3], aa);
                LDSM4(al[0], al[1], al[2], al[3], aa + TILE_B);
#pragma unroll
                for (int j = 0; j < 4; j++) {
                    MMA_BF16(c[i][j], ah, bh[j]);
                    MMA_BF16(c[i][j], ah, bl[j]);
                    MMA_BF16(c[i][j], al, bh[j]);
                }
            }
        }
        __syncthreads();
    }
#undef LOAD_STAGE

    // epilogue
    const int g = lid >> 2, t4 = lid & 3;
#pragma unroll
    for (int i = 0; i < 4; i++) {
        int r0 = bm + wm * 64 + i * 16 + g;
#pragma unroll
        for (int j = 0; j < 4; j++) {
            int col = bn + wn * 32 + j * 8 + t4 * 2;
            *(float2*)&C[(size_t)r0 * Nd + col] =
                make_float2(c[i][j][0], c[i][j][1]);
            *(float2*)&C[(size_t)(r0 + 8) * Nd + col] =
                make_float2(c[i][j][2], c[i][j][3]);
        }
    }
}

// ---------------------------------------------------------------------------
// RoPE (in place): pairs (i, i+64), angle = pos * theta^(-i/64), pos = row%SS
// ---------------------------------------------------------------------------
__global__ void rope_kernel(float* __restrict__ buf, int nheads) {
    int idx = blockIdx.x * blockDim.x + threadIdx.x;
    int total = MR * nheads * 64;
    if (idx >= total) return;
    int i    = idx & 63;
    int head = (idx >> 6) % nheads;
    int row  = idx / (nheads << 6);

    float p    = (float)(row % SS);
    float invf = expf(-(float)i * 0.14391156831212787f);
    float ang  = p * invf;
    float c, s;
    sincosf(ang, &s, &c);

    size_t base = (size_t)row * (nheads * HD) + head * HD + i;
    float x0 = buf[base];
    float x1 = buf[base + 64];
    buf[base]      = x0 * c - x1 * s;
    buf[base + 64] = x1 * c + x0 * s;
}

// ---------------------------------------------------------------------------
// Causal flash attention with GQA (fp32 SIMT, unchanged from R2)
// ---------------------------------------------------------------------------
#define BQ 64
#define BK 64
#define KP 132
#define PP 68
#define ATTN_SMEM ((BQ * KP + BK * KP + BK * HD + BQ * PP) * 4)

__global__ __launch_bounds__(256) void attn_kernel(const float* __restrict__ Q,
                                                   const float* __restrict__ Kg,
                                                   const float* __restrict__ Vg,
                                                   float* __restrict__ O) {
    extern __shared__ float sm[];
    float* Qs = sm;
    float* Ks = Qs + BQ * KP;
    float* Vs = Ks + BK * KP;
    float* Ps = Vs + BK * HD;

    const int tid = threadIdx.x;
    const int tx  = tid & 15;
    const int ty  = tid >> 4;
    const int qb  = blockIdx.x;
    const int h   = blockIdx.y;
    const int b   = blockIdx.z;
    const int kvh = h >> 2;
    const int q0  = qb * BQ;

#pragma unroll
    for (int i = 0; i < 8; i++) {
        int idx = i * 256 + tid;
        int r   = idx >> 5;
        int d4  = (idx & 31) << 2;
        *(float4*)&Qs[r * KP + d4] =
            *(const float4*)&Q[(size_t)(b * SS + q0 + r) * QD + h * HD + d4];
    }

    float m_i[4], l_i[4], acc[4][8];
#pragma unroll
    for (int i = 0; i < 4; i++) {
        m_i[i] = -1e30f;
        l_i[i] = 0.f;
#pragma unroll
        for (int d = 0; d < 8; d++) acc[i][d] = 0.f;
    }
    const float scale = 0.08838834764831845f;

    for (int kb = 0; kb <= qb; kb++) {
        const int k0 = kb * BK;
        __syncthreads();
#pragma unroll
        for (int i = 0; i < 8; i++) {
            int idx = i * 256 + tid;
            int r   = idx >> 5;
            int d4  = (idx & 31) << 2;
            size_t g = (size_t)(b * SS + k0 + r) * KVD + kvh * HD + d4;
            *(float4*)&Ks[r * KP + d4] = *(const float4*)&Kg[g];
            *(float4*)&Vs[r * HD + d4] = *(const float4*)&Vg[g];
        }
        __syncthreads();

        float sc[4][4];
#pragma unroll
        for (int i = 0; i < 4; i++)
#pragma unroll
            for (int j = 0; j < 4; j++) sc[i][j] = 0.f;

#pragma unroll 8
        for (int d4 = 0; d4 < HD; d4 += 4) {
            float4 qv[4], kv[4];
#pragma unroll
            for (int i = 0; i < 4; i++)
                qv[i] = *(float4*)&Qs[(ty * 4 + i) * KP + d4];
#pragma unroll
            for (int j = 0; j < 4; j++)
                kv[j] = *(float4*)&Ks[(tx + 16 * j) * KP + d4];
#pragma unroll
            for (int i = 0; i < 4; i++)
#pragma unroll
                for (int j = 0; j < 4; j++) {
                    sc[i][j] = fmaf(qv[i].x, kv[j].x, sc[i][j]);
                    sc[i][j] = fmaf(qv[i].y, kv[j].y, sc[i][j]);
                    sc[i][j] = fmaf(qv[i].z, kv[j].z, sc[i][j]);
                    sc[i][j] = fmaf(qv[i].w, kv[j].w, sc[i][j]);
                }
        }

#pragma unroll
        for (int i = 0; i < 4; i++) {
            int gr = q0 + ty * 4 + i;
#pragma unroll
            for (int j = 0; j < 4; j++) {
                int gc = k0 + tx + 16 * j;
                float v = sc[i][j] * scale;
                sc[i][j] = (gc > gr) ? -1e30f : v;
            }
        }

#pragma unroll
        for (int i = 0; i < 4; i++) {
            float mx = fmaxf(fmaxf(sc[i][0], sc[i][1]), fmaxf(sc[i][2], sc[i][3]));
#pragma unroll
            for (int off = 1; off < 16; off <<= 1)
                mx = fmaxf(mx, __shfl_xor_sync(0xffffffffu, mx, off));
            float m_new = fmaxf(m_i[i], mx);
            float corr  = __expf(m_i[i] - m_new);
            float rs = 0.f;
#pragma unroll
            for (int j = 0; j < 4; j++) {
                float p = __expf(sc[i][j] - m_new);
                sc[i][j] = p;
                rs += p;
            }
#pragma unroll
            for (int off = 1; off < 16; off <<= 1)
                rs += __shfl_xor_sync(0xffffffffu, rs, off);
            l_i[i] = l_i[i] * corr + rs;
            m_i[i] = m_new;
#pragma unroll
            for (int d = 0; d < 8; d++) acc[i][d] *= corr;
#pragma unroll
            for (int j = 0; j < 4; j++)
                Ps[(ty * 4 + i) * PP + tx + 16 * j] = sc[i][j];
        }
        __syncwarp();

#pragma unroll 4
        for (int c = 0; c < BK; c++) {
            float4 v0 = *(float4*)&Vs[c * HD + tx * 8];
            float4 v1 = *(float4*)&Vs[c * HD + tx * 8 + 4];
            float pr[4];
#pragma unroll
            for (int i = 0; i < 4; i++) pr[i] = Ps[(ty * 4 + i) * PP + c];
#pragma unroll
            for (int i = 0; i < 4; i++) {
                acc[i][0] = fmaf(pr[i], v0.x, acc[i][0]);
                acc[i][1] = fmaf(pr[i], v0.y, acc[i][1]);
                acc[i][2] = fmaf(pr[i], v0.z, acc[i][2]);
                acc[i][3] = fmaf(pr[i], v0.w, acc[i][3]);
                acc[i][4] = fmaf(pr[i], v1.x, acc[i][4]);
                acc[i][5] = fmaf(pr[i], v1.y, acc[i][5]);
                acc[i][6] = fmaf(pr[i], v1.z, acc[i][6]);
                acc[i][7] = fmaf(pr[i], v1.w, acc[i][7]);
            }
        }
    }

#pragma unroll
    for (int i = 0; i < 4; i++) {
        float il = 1.f / l_i[i];
        float4 o0 = make_float4(acc[i][0] * il, acc[i][1] * il,
                                acc[i][2] * il, acc[i][3] * il);
        float4 o1 = make_float4(acc[i][4] * il, acc[i][5] * il,
                                acc[i][6] * il, acc[i][7] * il);
        size_t g = (size_t)(b * SS + q0 + ty * 4 + i) * QD + h * HD + tx * 8;
        *(float4*)&O[g]     = o0;
        *(float4*)&O[g + 4] = o1;
    }
}

// ---------------------------------------------------------------------------
extern "C" void kernel_launch(void* const* d_in, const int* in_sizes, int n_in,
                              void* d_out, int out_size) {
    const float* hs  = (const float*)d_in[0];
    const float* Wq  = (const float*)d_in[2];
    const float* Wk  = (const float*)d_in[3];
    const float* Wv  = (const float*)d_in[4];
    const float* Wo  = (const float*)d_in[5];
    float*       out = (float*)d_out;

    float *qb, *kb, *vb, *ab;
    cudaGetSymbolAddress((void**)&qb, g_q);
    cudaGetSymbolAddress((void**)&kb, g_k);
    cudaGetSymbolAddress((void**)&vb, g_v);
    cudaGetSymbolAddress((void**)&ab, g_att);

    __nv_bfloat16 *hsh, *hsl, *wqh, *wql, *wkh, *wkl, *wvh, *wvl, *woh, *wol, *ath, *atl;
    cudaGetSymbolAddress((void**)&hsh, g_hs_h);
    cudaGetSymbolAddress((void**)&hsl, g_hs_l);
    cudaGetSymbolAddress((void**)&wqh, g_wqT_h);
    cudaGetSymbolAddress((void**)&wql, g_wqT_l);
    cudaGetSymbolAddress((void**)&wkh, g_wkT_h);
    cudaGetSymbolAddress((void**)&wkl, g_wkT_l);
    cudaGetSymbolAddress((void**)&wvh, g_wvT_h);
    cudaGetSymbolAddress((void**)&wvl, g_wvT_l);
    cudaGetSymbolAddress((void**)&woh, g_woT_h);
    cudaGetSymbolAddress((void**)&wol, g_woT_l);
    cudaGetSymbolAddress((void**)&ath, g_att_h);
    cudaGetSymbolAddress((void**)&atl, g_att_l);

    cudaFuncSetAttribute(mma_gemm, cudaFuncAttributeMaxDynamicSharedMemorySize, GEMM_SMEM);
    cudaFuncSetAttribute(attn_kernel, cudaFuncAttributeMaxDynamicSharedMemorySize, ATTN_SMEM);

    // split inputs to bf16 hi/lo
    split_kernel<<<(MR * HH / 4 + 255) / 256, 256>>>(hs, hsh, hsl, MR * HH / 4);
    split_transpose<<<dim3(QD / 32, HH / 32), dim3(32, 8)>>>(Wq, wqh, wql, HH, QD);
    split_transpose<<<dim3(KVD / 32, HH / 32), dim3(32, 8)>>>(Wk, wkh, wkl, HH, KVD);
    split_transpose<<<dim3(KVD / 32, HH / 32), dim3(32, 8)>>>(Wv, wvh, wvl, HH, KVD);
    split_transpose<<<dim3(HH / 32, QD / 32), dim3(32, 8)>>>(Wo, woh, wol, QD, HH);

    // QKV projections on tensor cores (mma.sync bf16x3)
    mma_gemm<<<dim3(QD / 128, MR / 128), 256, GEMM_SMEM>>>(hsh, hsl, wqh, wql, qb, QD, HH);
    mma_gemm<<<dim3(KVD / 128, MR / 128), 256, GEMM_SMEM>>>(hsh, hsl, wkh, wkl, kb, KVD, HH);
    mma_gemm<<<dim3(KVD / 128, MR / 128), 256, GEMM_SMEM>>>(hsh, hsl, wvh, wvl, vb, KVD, HH);

    // RoPE
    rope_kernel<<<(MR * NH * 64 + 255) / 256, 256>>>(qb, NH);
    rope_kernel<<<(MR * NKV * 64 + 255) / 256, 256>>>(kb, NKV);

    // causal GQA attention (fp32)
    attn_kernel<<<dim3(SS / BQ, NH, BB), 256, ATTN_SMEM>>>(qb, kb, vb, ab);

    // split attention output, then O projection on tensor cores
    split_kernel<<<(MR * QD / 4 + 255) / 256, 256>>>(ab, ath, atl, MR * QD / 4);
    mma_gemm<<<dim3(HH / 128, MR / 128), 256, GEMM_SMEM>>>(ath, atl, woh, wol, out, HH, QD);
}